// round 5
// baseline (speedup 1.0000x reference)
#include <cuda_runtime.h>

#define BB 4
#define LL 1024
#define VV 1280
#define NE 768
#define NB 8
#define NH 32
#define NO 256          // NB*NH
#define NC 32           // chunks over L
#define CH 32           // chunk size (NC*CH == LL)

typedef unsigned long long ull;

// packed fp32x2 FMA (SASS FFMA2) — PTX-only, ptxas never auto-fuses
__device__ __forceinline__ ull ffma2(ull a, ull b, ull c) {
    ull d;
    asm("fma.rn.f32x2 %0, %1, %2, %3;" : "=l"(d) : "l"(a), "l"(b), "l"(c));
    return d;
}

// Scratch (device globals: no allocation allowed)
__device__ float g_x[BB * LL * NO];           // 4 MB  : x = h @ W1
__device__ int   g_chunk_first[BB * NC * VV]; // 640 KB
__device__ int   g_next[BB * NC * VV];        // 640 KB

// ---------------------------------------------------------------------------
// GEMM1: x[4096,256] = h[4096,768] @ W1[768,256]
// Block 64m x 64n, 128 threads, thread tile 4m x 8n (4 f32x2 n-pairs).
// A is the broadcast operand -> stored DUPLICATED in smem ({a,a} pairs) so
// packed operands need no MOV. B pairs are natural from LDS.128.
// ---------------------------------------------------------------------------
__global__ __launch_bounds__(128) void gemm1_kernel(
    const float* __restrict__ h, const float* __restrict__ W1)
{
    __shared__ float As_dup[16][128];   // [k][2*m]: each a value stored twice
    __shared__ float Bs[16][64];        // [k][n]

    const int tid = threadIdx.x;
    const int tx = tid & 7;             // n group (8 n each)
    const int ty = tid >> 3;            // m group (4 m each), 0..15
    const int m0 = blockIdx.y * 64;
    const int n0 = blockIdx.x * 64;

    const int ar = tid >> 1;            // 0..63 (m row for A staging)
    const int ac = (tid & 1) * 8;       // 0 or 8 (k offset)
    const int br = tid >> 3;            // 0..15 (k row for B staging)
    const int bc = (tid & 7) * 8;       // n offset

    ull acc[4][4];                      // [m][n-pair]
#pragma unroll
    for (int i = 0; i < 4; ++i)
#pragma unroll
        for (int j = 0; j < 4; ++j) acc[i][j] = 0ULL;

    for (int k0 = 0; k0 < NE; k0 += 16) {
        // stage A duplicated: As_dup[k][2m]=As_dup[k][2m+1]=h[m][k]
#pragma unroll
        for (int half = 0; half < 2; ++half) {
            float4 av = *(const float4*)&h[(m0 + ar) * NE + k0 + ac + half * 4];
            ((float2*)As_dup[ac + half * 4 + 0])[ar] = make_float2(av.x, av.x);
            ((float2*)As_dup[ac + half * 4 + 1])[ar] = make_float2(av.y, av.y);
            ((float2*)As_dup[ac + half * 4 + 2])[ar] = make_float2(av.z, av.z);
            ((float2*)As_dup[ac + half * 4 + 3])[ar] = make_float2(av.w, av.w);
        }
        // stage B natural
#pragma unroll
        for (int half = 0; half < 2; ++half) {
            *(float4*)&Bs[br][bc + half * 4] =
                *(const float4*)&W1[(k0 + br) * NO + n0 + bc + half * 4];
        }
        __syncthreads();

#pragma unroll
        for (int kk = 0; kk < 16; ++kk) {
            const ull* arow = (const ull*)As_dup[kk];   // 64 dup-pairs
            const ull* brow = (const ull*)Bs[kk];       // 32 natural pairs
            ulonglong2 t0 = *(const ulonglong2*)&arow[ty * 4];
            ulonglong2 t1 = *(const ulonglong2*)&arow[ty * 4 + 2];
            ulonglong2 u0 = *(const ulonglong2*)&brow[tx * 4];
            ulonglong2 u1 = *(const ulonglong2*)&brow[tx * 4 + 2];
            ull a_[4] = {t0.x, t0.y, t1.x, t1.y};
            ull b_[4] = {u0.x, u0.y, u1.x, u1.y};
#pragma unroll
            for (int i = 0; i < 4; ++i)
#pragma unroll
                for (int j = 0; j < 4; ++j)
                    acc[i][j] = ffma2(a_[i], b_[j], acc[i][j]);
        }
        __syncthreads();
    }

#pragma unroll
    for (int i = 0; i < 4; ++i) {
        ull* orow = (ull*)&g_x[(m0 + ty * 4 + i) * NO + n0 + tx * 8];
        *(ulonglong2*)&orow[0] = make_ulonglong2(acc[i][0], acc[i][1]);
        *(ulonglong2*)&orow[2] = make_ulonglong2(acc[i][2], acc[i][3]);
    }
}

// ---------------------------------------------------------------------------
// GEMM2: logits[m][n][v] = sum_h x[m][n*32+h] * W2[h][v]
// Block: 8 m-rows x 256 v x all 8 bins. 256 threads = 8 warps.
// Warp: wm = wid>>1 (2 m rows), wv = wid&1 (128-v half). Lane: 4 v (2 pairs).
// x is broadcast -> stored duplicated in smem; W2 pairs natural from LDS.128.
// ---------------------------------------------------------------------------
__global__ __launch_bounds__(256) void gemm2_kernel(
    const float* __restrict__ W2, float* __restrict__ logits)
{
    __shared__ float  W2s[32][256];     // 32 KB
    __shared__ float2 xs[8 * 256];      // 16 KB, dup'd {x,x}

    const int tid = threadIdx.x;
    const int v0 = blockIdx.x * 256;
    const int m0 = blockIdx.y * 8;
    const int wid = tid >> 5;
    const int lane = tid & 31;
    const int wm = wid >> 1;            // 0..3
    const int wv = wid & 1;
    const int vloc = wv * 128 + lane * 4;

    // stage W2 tile: 32x256
#pragma unroll
    for (int it = 0; it < 8; ++it) {
        int f4 = tid + it * 256;        // 0..2047 float4s
        int r = f4 >> 6;                // 0..31
        int c = (f4 & 63) * 4;
        *(float4*)&W2s[r][c] = *(const float4*)&W2[r * VV + v0 + c];
    }
    // stage x duplicated: 8 rows x 256
#pragma unroll
    for (int it = 0; it < 8; ++it) {
        int idx = tid + it * 256;       // 0..2047
        int r = idx >> 8;
        int c = idx & 255;
        float v = g_x[(m0 + r) * NO + c];
        xs[r * 256 + c] = make_float2(v, v);
    }
    __syncthreads();

    ull acc[2][8][2];
#pragma unroll
    for (int mi = 0; mi < 2; ++mi)
#pragma unroll
        for (int n = 0; n < 8; ++n) { acc[mi][n][0] = 0ULL; acc[mi][n][1] = 0ULL; }

#pragma unroll
    for (int h4 = 0; h4 < 8; ++h4) {
        const int hh = h4 * 4;
        ull w_[4][2];
#pragma unroll
        for (int j = 0; j < 4; ++j) {
            ulonglong2 wt = *(const ulonglong2*)&W2s[hh + j][vloc];
            w_[j][0] = wt.x; w_[j][1] = wt.y;
        }
#pragma unroll
        for (int mi = 0; mi < 2; ++mi) {
            const ull* xrow = (const ull*)&xs[(wm * 2 + mi) * 256];
#pragma unroll
            for (int n = 0; n < 8; ++n) {
                ulonglong2 x0 = *(const ulonglong2*)&xrow[n * 32 + hh];
                ulonglong2 x1 = *(const ulonglong2*)&xrow[n * 32 + hh + 2];
                ull xd[4] = {x0.x, x0.y, x1.x, x1.y};
#pragma unroll
                for (int j = 0; j < 4; ++j) {
                    acc[mi][n][0] = ffma2(xd[j], w_[j][0], acc[mi][n][0]);
                    acc[mi][n][1] = ffma2(xd[j], w_[j][1], acc[mi][n][1]);
                }
            }
        }
    }

#pragma unroll
    for (int mi = 0; mi < 2; ++mi) {
        const int m = m0 + wm * 2 + mi;
#pragma unroll
        for (int n = 0; n < 8; ++n) {
            *(ulonglong2*)&logits[(m * NB + n) * VV + v0 + vloc] =
                make_ulonglong2(acc[mi][n][0], acc[mi][n][1]);
        }
    }
}

// ---------------------------------------------------------------------------
// Kernel A: per-chunk first occurrence. Block per (b, c); smem atomicMin.
// ---------------------------------------------------------------------------
__global__ __launch_bounds__(256) void first_occ_kernel(const int* __restrict__ targets)
{
    __shared__ int arr[VV];
    const int b = blockIdx.x >> 5;
    const int c = blockIdx.x & 31;
    const int tid = threadIdx.x;

#pragma unroll
    for (int it = 0; it < 5; ++it) arr[tid + it * 256] = LL;
    __syncthreads();
    if (tid < CH) {
        int j = c * CH + tid;
        atomicMin(&arr[targets[b * LL + j]], j);
    }
    __syncthreads();
#pragma unroll
    for (int it = 0; it < 5; ++it) {
        int idx = tid + it * 256;
        g_chunk_first[(b * NC + c) * VV + idx] = arr[idx];
    }
}

// ---------------------------------------------------------------------------
// Kernel B: exclusive suffix-min over chunks. One thread per (b, v).
// ---------------------------------------------------------------------------
__global__ __launch_bounds__(256) void suffix_kernel()
{
    const int gt = blockIdx.x * 256 + threadIdx.x;   // 0..5119
    const int b = gt / VV;
    const int v = gt - b * VV;

    int cf[NC];
#pragma unroll
    for (int c = 0; c < NC; ++c) cf[c] = g_chunk_first[(b * NC + c) * VV + v];

    int run = LL;
#pragma unroll
    for (int c = NC - 1; c >= 0; --c) {
        g_next[(b * NC + c) * VV + v] = run;
        run = min(run, cf[c]);
    }
}

// ---------------------------------------------------------------------------
// Kernel C: tte + censor mask. Block per (b, c, vhalf), 160 threads, 4 v each.
// ---------------------------------------------------------------------------
__global__ __launch_bounds__(160) void tte_mask_kernel(
    const int* __restrict__ targets,
    const float* __restrict__ age,
    const float* __restrict__ targets_age,
    float* __restrict__ out_tte,
    float* __restrict__ out_mask)
{
    __shared__ float ta_s[LL];
    __shared__ int ts[CH];
    __shared__ float ag[CH];

    const int b = blockIdx.x >> 6;
    const int rem = blockIdx.x & 63;
    const int c = rem >> 1;
    const int half = rem & 1;
    const int tid = threadIdx.x;        // 0..159

    for (int idx = tid; idx < LL; idx += 160)
        ta_s[idx] = targets_age[b * LL + idx];
    if (tid < CH) {
        int i = c * CH + tid;
        ts[tid] = targets[b * LL + i];
        ag[tid] = age[b * LL + i];
    }
    __syncthreads();

    const int vb = half * 640 + tid * 4;
    int4 c4 = *(const int4*)&g_next[(b * NC + c) * VV + vb];
    int cur0 = c4.x, cur1 = c4.y, cur2 = c4.z, cur3 = c4.w;

    for (int jj = CH - 1; jj >= 0; --jj) {
        const int i = c * CH + jj;
        const int t = ts[jj];
        const float ai = ag[jj];

        if (t == vb + 0) cur0 = i;
        if (t == vb + 1) cur1 = i;
        if (t == vb + 2) cur2 = i;
        if (t == vb + 3) cur3 = i;

        float tte[4];
        bool nev[4];
        int curs[4] = {cur0, cur1, cur2, cur3};
#pragma unroll
        for (int q = 0; q < 4; ++q) {
            int vv = vb + q;
            int idxr = curs[q];
            if (vv == 0 && i > 0) idxr = 0;  // reference's where(upper, targets, 0) quirk
            bool ne = (idxr == LL);
            int idx = ne ? (LL - 1) : idxr;
            tte[q] = ta_s[idx] - ai;
            nev[q] = ne;
        }

        const int row = b * LL + i;
        *(float4*)&out_tte[row * VV + vb] = make_float4(tte[0], tte[1], tte[2], tte[3]);

        int bin[4];
        bool valid[4];
#pragma unroll
        for (int q = 0; q < 4; ++q) {
            float tq = tte[q];
            valid[q] = (tq >= 0.0f) && (tq < 10.0f);
            bin[q] = (tq >= 1.25f) + (tq >= 2.5f) + (tq >= 3.75f) + (tq >= 5.0f)
                   + (tq >= 6.25f) + (tq >= 7.5f) + (tq >= 8.75f);
        }

        const int mbase = row * NB * VV + vb;
#pragma unroll
        for (int n = 0; n < 8; ++n) {
            float4 mv;
            mv.x = (nev[0] || (valid[0] && bin[0] == n)) ? 1.0f : 0.0f;
            mv.y = (nev[1] || (valid[1] && bin[1] == n)) ? 1.0f : 0.0f;
            mv.z = (nev[2] || (valid[2] && bin[2] == n)) ? 1.0f : 0.0f;
            mv.w = (nev[3] || (valid[3] && bin[3] == n)) ? 1.0f : 0.0f;
            *(float4*)&out_mask[mbase + n * VV] = mv;
        }
    }
}

// ---------------------------------------------------------------------------
extern "C" void kernel_launch(void* const* d_in, const int* in_sizes, int n_in,
                              void* d_out, int out_size)
{
    const float* h   = (const float*)d_in[0];  // (B,L,768) f32
    const float* age = (const float*)d_in[1];  // (B,L) f32
    const float* ta  = (const float*)d_in[2];  // (B,L) f32 targets_age
    // d_in[3] = delta_t (unused by outputs)
    const int*   tg  = (const int*)d_in[4];    // (B,L) i32 targets
    const float* W1  = (const float*)d_in[5];  // (768,256) f32
    const float* W2  = (const float*)d_in[6];  // (32,1280) f32

    float* out = (float*)d_out;
    float* out_logits = out;                                  // B*L*8*V
    float* out_tte    = out + (size_t)BB * LL * NB * VV;      // B*L*V
    float* out_mask   = out_tte + (size_t)BB * LL * VV;       // B*L*8*V

    gemm1_kernel<<<dim3(NO / 64, (BB * LL) / 64), 128>>>(h, W1);
    gemm2_kernel<<<dim3(VV / 256, (BB * LL) / 8), 256>>>(W2, out_logits);
    first_occ_kernel<<<BB * NC, 256>>>(tg);
    suffix_kernel<<<(BB * VV) / 256, 256>>>();
    tte_mask_kernel<<<BB * NC * 2, 160>>>(tg, age, ta, out_tte, out_mask);
}

// round 6
// speedup vs baseline: 1.0959x; 1.0959x over previous
#include <cuda_runtime.h>

#define BB 4
#define LL 1024
#define VV 1280
#define NE 768
#define NB 8
#define NH 32
#define NO 256          // NB*NH
#define NC 32           // chunks over L
#define CH 32           // chunk size (NC*CH == LL)

typedef unsigned long long ull;

// packed fp32x2 FMA (SASS FFMA2) — PTX-only; IEEE-identical to 2x fmaf
__device__ __forceinline__ ull ffma2(ull a, ull b, ull c) {
    ull d;
    asm("fma.rn.f32x2 %0, %1, %2, %3;" : "=l"(d) : "l"(a), "l"(b), "l"(c));
    return d;
}

// Scratch (device globals: no allocation allowed)
__device__ float g_x[BB * LL * NO];           // 4 MB  : x = h @ W1
__device__ int   g_chunk_first[BB * NC * VV]; // 640 KB
__device__ int   g_next[BB * NC * VV];        // 640 KB

// ---------------------------------------------------------------------------
// GEMM1: x[4096,256] = h[4096,768] @ W1[768,256]
// Block 128m x 64n, 256 threads (8 warps), BK=16.
// Thread tile 8m x 4n  ->  16 FFMA2 per kk, acc = 16 ull (32 regs).
// A (broadcast operand) stored DUPLICATED in smem ({a,a} float2 pairs).
// ---------------------------------------------------------------------------
__global__ __launch_bounds__(256) void gemm1_kernel(
    const float* __restrict__ h, const float* __restrict__ W1)
{
    __shared__ float As_dup[16][256];   // [k][2*m] : 16 KB
    __shared__ float Bs[16][64];        // [k][n]   :  4 KB

    const int tid = threadIdx.x;
    const int tx = tid & 15;            // n group: 4 n each
    const int ty = tid >> 4;            // m group: 8 m each (0..15)
    const int m0 = blockIdx.y * 128;
    const int n0 = blockIdx.x * 64;

    const int ar = tid >> 1;            // 0..127 (m for A staging)
    const int ac = (tid & 1) * 8;       // 0 or 8 (k offset)
    const int br = tid >> 4;            // 0..15  (k for B staging)
    const int bc = (tid & 15) * 4;      // n offset

    ull acc[8][2];                      // [m][n-pair]
#pragma unroll
    for (int i = 0; i < 8; ++i) { acc[i][0] = 0ULL; acc[i][1] = 0ULL; }

    for (int k0 = 0; k0 < NE; k0 += 16) {
#pragma unroll
        for (int half = 0; half < 2; ++half) {
            float4 av = *(const float4*)&h[(m0 + ar) * NE + k0 + ac + half * 4];
            ((float2*)As_dup[ac + half * 4 + 0])[ar] = make_float2(av.x, av.x);
            ((float2*)As_dup[ac + half * 4 + 1])[ar] = make_float2(av.y, av.y);
            ((float2*)As_dup[ac + half * 4 + 2])[ar] = make_float2(av.z, av.z);
            ((float2*)As_dup[ac + half * 4 + 3])[ar] = make_float2(av.w, av.w);
        }
        *(float4*)&Bs[br][bc] = *(const float4*)&W1[(k0 + br) * NO + n0 + bc];
        __syncthreads();

#pragma unroll
        for (int kk = 0; kk < 16; ++kk) {
            const ull* arow = (const ull*)As_dup[kk];   // 128 dup-pairs
            const ull* brow = (const ull*)Bs[kk];       // 32 natural pairs
            ulonglong2 t0 = *(const ulonglong2*)&arow[ty * 8 + 0];
            ulonglong2 t1 = *(const ulonglong2*)&arow[ty * 8 + 2];
            ulonglong2 t2 = *(const ulonglong2*)&arow[ty * 8 + 4];
            ulonglong2 t3 = *(const ulonglong2*)&arow[ty * 8 + 6];
            ulonglong2 u  = *(const ulonglong2*)&brow[tx * 2];
            ull a_[8] = {t0.x, t0.y, t1.x, t1.y, t2.x, t2.y, t3.x, t3.y};
#pragma unroll
            for (int i = 0; i < 8; ++i) {
                acc[i][0] = ffma2(a_[i], u.x, acc[i][0]);
                acc[i][1] = ffma2(a_[i], u.y, acc[i][1]);
            }
        }
        __syncthreads();
    }

#pragma unroll
    for (int i = 0; i < 8; ++i) {
        *(ulonglong2*)&g_x[(m0 + ty * 8 + i) * NO + n0 + tx * 4] =
            make_ulonglong2(acc[i][0], acc[i][1]);
    }
}

// ---------------------------------------------------------------------------
// GEMM2: logits[m][n][v] = sum_h x[m][n*32+h] * W2[h][v]
// Block: 8 m-rows x 128 v x all 8 bins. 256 threads = 8 warps.
// Warp wid owns m-row wid; lane owns 4 v (2 f32x2 pairs).
// acc = 8n x 2vp = 16 ull (32 regs). x broadcast (dup'd smem), w natural pairs.
// ---------------------------------------------------------------------------
__global__ __launch_bounds__(256) void gemm2_kernel(
    const float* __restrict__ W2, float* __restrict__ logits)
{
    __shared__ float  W2s[32][128];     // 16 KB
    __shared__ float2 xs[8 * 256];      // 16 KB, dup'd {x,x}

    const int tid = threadIdx.x;
    const int v0 = blockIdx.x * 128;
    const int m0 = blockIdx.y * 8;
    const int wid = tid >> 5;           // m-row within block
    const int lane = tid & 31;
    const int vloc = lane * 4;

    // stage W2 tile: 32 x 128
#pragma unroll
    for (int it = 0; it < 4; ++it) {
        int f4 = tid + it * 256;        // 0..1023 float4s
        int r = f4 >> 5;                // 0..31
        int c = (f4 & 31) * 4;
        *(float4*)&W2s[r][c] = *(const float4*)&W2[r * VV + v0 + c];
    }
    // stage x duplicated: 8 rows x 256
#pragma unroll
    for (int it = 0; it < 8; ++it) {
        int idx = tid + it * 256;       // 0..2047
        int r = idx >> 8;
        int c = idx & 255;
        float v = g_x[(m0 + r) * NO + c];
        xs[r * 256 + c] = make_float2(v, v);
    }
    __syncthreads();

    ull acc[8][2];
#pragma unroll
    for (int n = 0; n < 8; ++n) { acc[n][0] = 0ULL; acc[n][1] = 0ULL; }

    const ull* xrow = (const ull*)&xs[wid * 256];   // dup-pair per h-col

#pragma unroll
    for (int h4 = 0; h4 < 8; ++h4) {
        const int hh = h4 * 4;
        ull w_[4][2];
#pragma unroll
        for (int j = 0; j < 4; ++j) {
            ulonglong2 wt = *(const ulonglong2*)&W2s[hh + j][vloc];
            w_[j][0] = wt.x; w_[j][1] = wt.y;
        }
#pragma unroll
        for (int n = 0; n < 8; ++n) {
            ulonglong2 x0 = *(const ulonglong2*)&xrow[n * 32 + hh];      // h, h+1
            ulonglong2 x1 = *(const ulonglong2*)&xrow[n * 32 + hh + 2];  // h+2, h+3
            acc[n][0] = ffma2(x0.x, w_[0][0], acc[n][0]);
            acc[n][1] = ffma2(x0.x, w_[0][1], acc[n][1]);
            acc[n][0] = ffma2(x0.y, w_[1][0], acc[n][0]);
            acc[n][1] = ffma2(x0.y, w_[1][1], acc[n][1]);
            acc[n][0] = ffma2(x1.x, w_[2][0], acc[n][0]);
            acc[n][1] = ffma2(x1.x, w_[2][1], acc[n][1]);
            acc[n][0] = ffma2(x1.y, w_[3][0], acc[n][0]);
            acc[n][1] = ffma2(x1.y, w_[3][1], acc[n][1]);
        }
    }

    const int m = m0 + wid;
#pragma unroll
    for (int n = 0; n < 8; ++n) {
        *(ulonglong2*)&logits[(m * NB + n) * VV + v0 + vloc] =
            make_ulonglong2(acc[n][0], acc[n][1]);
    }
}

// ---------------------------------------------------------------------------
// Kernel A: per-chunk first occurrence. Block per (b, c); smem atomicMin.
// ---------------------------------------------------------------------------
__global__ __launch_bounds__(256) void first_occ_kernel(const int* __restrict__ targets)
{
    __shared__ int arr[VV];
    const int b = blockIdx.x >> 5;
    const int c = blockIdx.x & 31;
    const int tid = threadIdx.x;

#pragma unroll
    for (int it = 0; it < 5; ++it) arr[tid + it * 256] = LL;
    __syncthreads();
    if (tid < CH) {
        int j = c * CH + tid;
        atomicMin(&arr[targets[b * LL + j]], j);
    }
    __syncthreads();
#pragma unroll
    for (int it = 0; it < 5; ++it) {
        int idx = tid + it * 256;
        g_chunk_first[(b * NC + c) * VV + idx] = arr[idx];
    }
}

// ---------------------------------------------------------------------------
// Kernel B: exclusive suffix-min over chunks. One thread per (b, v).
// ---------------------------------------------------------------------------
__global__ __launch_bounds__(256) void suffix_kernel()
{
    const int gt = blockIdx.x * 256 + threadIdx.x;   // 0..5119
    const int b = gt / VV;
    const int v = gt - b * VV;

    int cf[NC];
#pragma unroll
    for (int c = 0; c < NC; ++c) cf[c] = g_chunk_first[(b * NC + c) * VV + v];

    int run = LL;
#pragma unroll
    for (int c = NC - 1; c >= 0; --c) {
        g_next[(b * NC + c) * VV + v] = run;
        run = min(run, cf[c]);
    }
}

// ---------------------------------------------------------------------------
// Kernel C: tte + censor mask. Block per (b, c, vhalf), 160 threads, 4 v each.
// ---------------------------------------------------------------------------
__global__ __launch_bounds__(160) void tte_mask_kernel(
    const int* __restrict__ targets,
    const float* __restrict__ age,
    const float* __restrict__ targets_age,
    float* __restrict__ out_tte,
    float* __restrict__ out_mask)
{
    __shared__ float ta_s[LL];
    __shared__ int ts[CH];
    __shared__ float ag[CH];

    const int b = blockIdx.x >> 6;
    const int rem = blockIdx.x & 63;
    const int c = rem >> 1;
    const int half = rem & 1;
    const int tid = threadIdx.x;        // 0..159

    for (int idx = tid; idx < LL; idx += 160)
        ta_s[idx] = targets_age[b * LL + idx];
    if (tid < CH) {
        int i = c * CH + tid;
        ts[tid] = targets[b * LL + i];
        ag[tid] = age[b * LL + i];
    }
    __syncthreads();

    const int vb = half * 640 + tid * 4;
    int4 c4 = *(const int4*)&g_next[(b * NC + c) * VV + vb];
    int cur0 = c4.x, cur1 = c4.y, cur2 = c4.z, cur3 = c4.w;

    for (int jj = CH - 1; jj >= 0; --jj) {
        const int i = c * CH + jj;
        const int t = ts[jj];
        const float ai = ag[jj];

        if (t == vb + 0) cur0 = i;
        if (t == vb + 1) cur1 = i;
        if (t == vb + 2) cur2 = i;
        if (t == vb + 3) cur3 = i;

        float tte[4];
        bool nev[4];
        int curs[4] = {cur0, cur1, cur2, cur3};
#pragma unroll
        for (int q = 0; q < 4; ++q) {
            int vv = vb + q;
            int idxr = curs[q];
            if (vv == 0 && i > 0) idxr = 0;  // reference's where(upper, targets, 0) quirk
            bool ne = (idxr == LL);
            int idx = ne ? (LL - 1) : idxr;
            tte[q] = ta_s[idx] - ai;
            nev[q] = ne;
        }

        const int row = b * LL + i;
        *(float4*)&out_tte[row * VV + vb] = make_float4(tte[0], tte[1], tte[2], tte[3]);

        int bin[4];
        bool valid[4];
#pragma unroll
        for (int q = 0; q < 4; ++q) {
            float tq = tte[q];
            valid[q] = (tq >= 0.0f) && (tq < 10.0f);
            bin[q] = (tq >= 1.25f) + (tq >= 2.5f) + (tq >= 3.75f) + (tq >= 5.0f)
                   + (tq >= 6.25f) + (tq >= 7.5f) + (tq >= 8.75f);
        }

        const int mbase = row * NB * VV + vb;
#pragma unroll
        for (int n = 0; n < 8; ++n) {
            float4 mv;
            mv.x = (nev[0] || (valid[0] && bin[0] == n)) ? 1.0f : 0.0f;
            mv.y = (nev[1] || (valid[1] && bin[1] == n)) ? 1.0f : 0.0f;
            mv.z = (nev[2] || (valid[2] && bin[2] == n)) ? 1.0f : 0.0f;
            mv.w = (nev[3] || (valid[3] && bin[3] == n)) ? 1.0f : 0.0f;
            *(float4*)&out_mask[mbase + n * VV] = mv;
        }
    }
}

// ---------------------------------------------------------------------------
extern "C" void kernel_launch(void* const* d_in, const int* in_sizes, int n_in,
                              void* d_out, int out_size)
{
    const float* h   = (const float*)d_in[0];  // (B,L,768) f32
    const float* age = (const float*)d_in[1];  // (B,L) f32
    const float* ta  = (const float*)d_in[2];  // (B,L) f32 targets_age
    // d_in[3] = delta_t (unused by outputs)
    const int*   tg  = (const int*)d_in[4];    // (B,L) i32 targets
    const float* W1  = (const float*)d_in[5];  // (768,256) f32
    const float* W2  = (const float*)d_in[6];  // (32,1280) f32

    float* out = (float*)d_out;
    float* out_logits = out;                                  // B*L*8*V
    float* out_tte    = out + (size_t)BB * LL * NB * VV;      // B*L*V
    float* out_mask   = out_tte + (size_t)BB * LL * VV;       // B*L*8*V

    // order chosen so the ncu-captured slot (4th of a replay) lands on gemm2
    first_occ_kernel<<<BB * NC, 256>>>(tg);
    gemm1_kernel<<<dim3(NO / 64, (BB * LL) / 128), 256>>>(h, W1);
    suffix_kernel<<<(BB * VV) / 256, 256>>>();
    gemm2_kernel<<<dim3(VV / 128, (BB * LL) / 8), 256>>>(W2, out_logits);
    tte_mask_kernel<<<BB * NC * 2, 160>>>(tg, age, ta, out_tte, out_mask);
}